// round 2
// baseline (speedup 1.0000x reference)
#include <cuda_runtime.h>
#include <cstdint>

#define NB 64
#define NS 512
#define NH 768
#define NL 9

// scratch (static device globals — no allocation)
__device__ float g_feats[NB * NS * NL];
__device__ float g_nll[NB];

__device__ __forceinline__ unsigned long long ffma2(unsigned long long a,
                                                    unsigned long long b,
                                                    unsigned long long c) {
    unsigned long long d;
    asm("fma.rn.f32x2 %0, %1, %2, %3;" : "=l"(d) : "l"(a), "l"(b), "l"(c));
    return d;
}

// ---------------------------------------------------------------------------
// Phase 1: feats[tok][l] = hidden[tok] . W[l] + b[l]
// 4 tokens per warp; W chunk reused across the 4 tokens. Packed f32x2 FMA
// halves FFMA issue -> phase is DRAM-bound (~100 MB of hidden).
// ---------------------------------------------------------------------------
__global__ __launch_bounds__(256) void gemm_kernel(
    const float* __restrict__ hidden, const float* __restrict__ W,
    const float* __restrict__ bias)
{
    int gw   = (blockIdx.x * 256 + threadIdx.x) >> 5;   // global warp id, 0..8191
    int lane = threadIdx.x & 31;
    int tok0 = gw * 4;

    unsigned long long acc[4][NL];
#pragma unroll
    for (int t = 0; t < 4; t++)
#pragma unroll
        for (int l = 0; l < NL; l++) acc[t][l] = 0ull;

#pragma unroll
    for (int c = 0; c < 6; c++) {
        int h = c * 128 + lane * 4;          // warp covers 128 h-cols per chunk
        double2 hv[4];
#pragma unroll
        for (int t = 0; t < 4; t++)
            hv[t] = __ldg((const double2*)(hidden + (size_t)(tok0 + t) * NH + h));
#pragma unroll
        for (int l = 0; l < NL; l++) {
            double2 wv = __ldg((const double2*)(W + l * NH + h));
            unsigned long long wlo = (unsigned long long)__double_as_longlong(wv.x);
            unsigned long long whi = (unsigned long long)__double_as_longlong(wv.y);
#pragma unroll
            for (int t = 0; t < 4; t++) {
                acc[t][l] = ffma2((unsigned long long)__double_as_longlong(hv[t].x), wlo, acc[t][l]);
                acc[t][l] = ffma2((unsigned long long)__double_as_longlong(hv[t].y), whi, acc[t][l]);
            }
        }
    }

#pragma unroll
    for (int t = 0; t < 4; t++) {
#pragma unroll
        for (int l = 0; l < NL; l++) {
            float lo, hi;
            asm("mov.b64 {%0, %1}, %2;" : "=f"(lo), "=f"(hi) : "l"(acc[t][l]));
            float v = lo + hi;
#pragma unroll
            for (int o = 16; o > 0; o >>= 1)
                v += __shfl_xor_sync(0xffffffffu, v, o);
            int oidx = t * NL + l;
            if (lane == (oidx & 31)) {
                g_feats[(size_t)(tok0 + t) * NL + l] = v + __ldg(bias + l);
            }
        }
    }
}

// ---------------------------------------------------------------------------
// dtype-agnostic mask length (mask values are 0/1; layout may be 1-byte bool
// or 4-byte int32/float32 — harness marshalling is only guaranteed for the
// 4-byte types). Probe: byte[1] of the buffer nonzero <=> 1-byte layout
// (element 1 is always true because len >= S/2 = 256). For 4-byte layouts
// that byte is 0 (int 1 = 01 00 00 00, float 1.0 = 00 00 80 3f).
// Counting nonzero 32-bit words covers both int32 and float32.
// ---------------------------------------------------------------------------
__device__ __forceinline__ int mask_len_warp(const unsigned char* mask, int b, int lane) {
    int c = 0;
    if (mask[1] != 0) {
        // 1-byte layout
        const uint4* mp = (const uint4*)(mask + (size_t)b * NS);
        uint4 mv = mp[lane];                 // 16 bytes per lane
        c = __dp4a((int)mv.x, 0x01010101, c);
        c = __dp4a((int)mv.y, 0x01010101, c);
        c = __dp4a((int)mv.z, 0x01010101, c);
        c = __dp4a((int)mv.w, 0x01010101, c);
    } else {
        // 4-byte layout (int32 or float32): count nonzero words
        const uint4* mp = (const uint4*)((const uint32_t*)mask + (size_t)b * NS);
#pragma unroll
        for (int k = 0; k < 4; k++) {
            uint4 mv = mp[lane * 4 + k];     // 4 words per load, 16 words per lane
            c += (mv.x != 0u) + (mv.y != 0u) + (mv.z != 0u) + (mv.w != 0u);
        }
    }
#pragma unroll
    for (int o = 16; o > 0; o >>= 1) c += __shfl_xor_sync(0xffffffffu, c, o);
    return c;
}

// ---------------------------------------------------------------------------
// Phase 2: per-batch CRF forward scan (warp 0) + gold-path score (warp 1).
// Exp-domain recurrence: q'_j = (sum_i q_i * exp(trans[i][j])) * exp(f_t[j]),
// alpha = C + log q, renormalized every 8 steps. Mask is a prefix -> loop to len.
// ---------------------------------------------------------------------------
__global__ __launch_bounds__(128) void crf_kernel(
    const float* __restrict__ startv, const float* __restrict__ endv,
    const float* __restrict__ trans, const int* __restrict__ labels,
    const unsigned char* __restrict__ mask)
{
    __shared__ float s_ef[NS * NL];          // exp(feats) for this batch row
    __shared__ float s_trans[NL * NL];
    __shared__ float s_score, s_logden;

    int b    = blockIdx.x;
    int tid  = threadIdx.x;
    int lane = tid & 31;
    int wid  = tid >> 5;

    const float* fb = g_feats + (size_t)b * NS * NL;

    // preload exp(feats) into smem (all 128 threads)
    {
        const float4* src = (const float4*)fb;
        float4*       dst = (float4*)s_ef;
        for (int i = tid; i < NS * NL / 4; i += 128) {
            float4 v = __ldg(src + i);
            float4 e;
            e.x = __expf(v.x); e.y = __expf(v.y);
            e.z = __expf(v.z); e.w = __expf(v.w);
            dst[i] = e;
        }
    }
    if (tid < NL * NL) s_trans[tid] = trans[tid];
    __syncthreads();

    int len = mask_len_warp(mask, b, lane);

    if (wid == 0) {
        // ----- forward scan -----
        int jc = lane < NL ? lane : NL - 1;  // lanes 9..31 duplicate lane 8 (harmless)
        float Ecol[NL];
#pragma unroll
        for (int i = 0; i < NL; i++) Ecol[i] = __expf(s_trans[i * NL + jc]);

        float a0 = __ldg(startv + jc) + fb[jc];
        float C  = __shfl_sync(0xffffffffu, a0, 0);
        float qn = __expf(a0 - C);
        float q[NL];
#pragma unroll
        for (int i = 0; i < NL; i++) q[i] = __shfl_sync(0xffffffffu, qn, i);

        float eft = s_ef[NL + jc];           // prefetch t=1 (len >= 256 always)
        for (int t = 1; t < len; t++) {
            int   tn  = (t + 1 < NS) ? t + 1 : NS - 1;
            float efn = s_ef[tn * NL + jc];  // prefetch next step

            float p0 = q[0]*Ecol[0], p1 = q[1]*Ecol[1], p2 = q[2]*Ecol[2];
            float p3 = q[3]*Ecol[3], p4 = q[4]*Ecol[4], p5 = q[5]*Ecol[5];
            float p6 = q[6]*Ecol[6], p7 = q[7]*Ecol[7], p8 = q[8]*Ecol[8];
            float s  = (((p0 + p1) + (p2 + p3)) + ((p4 + p5) + (p6 + p7))) + p8;
            qn = s * eft;
#pragma unroll
            for (int i = 0; i < NL; i++) q[i] = __shfl_sync(0xffffffffu, qn, i);
            eft = efn;

            if ((t & 7) == 0) {              // renormalize every 8 steps
                float r   = q[0];
                C        += __logf(r);
                float inv = __fdividef(1.0f, r);
#pragma unroll
                for (int i = 0; i < NL; i++) q[i] *= inv;
            }
        }

        float term = (lane < NL) ? q[jc] * __expf(__ldg(endv + jc)) : 0.0f;
#pragma unroll
        for (int o = 16; o > 0; o >>= 1)
            term += __shfl_xor_sync(0xffffffffu, term, o);
        if (lane == 0) s_logden = C + __logf(term);
    } else if (wid == 1) {
        // ----- gold-path score -----
        const int* lab = labels + (size_t)b * NS;
        float sc = 0.0f;
        for (int t = lane; t < NS; t += 32) {
            if (t >= 1 && t < len) {
                int lp = __ldg(lab + t - 1);
                int lc = __ldg(lab + t);
                sc += s_trans[lp * NL + lc] + fb[t * NL + lc];
            }
        }
        if (lane == 0) {
            int l0 = __ldg(lab);
            sc += __ldg(startv + l0) + fb[l0];
            sc += __ldg(endv + __ldg(lab + len - 1));
        }
#pragma unroll
        for (int o = 16; o > 0; o >>= 1)
            sc += __shfl_xor_sync(0xffffffffu, sc, o);
        if (lane == 0) s_score = sc;
    }
    __syncthreads();
    if (tid == 0) g_nll[b] = s_logden - s_score;
}

// ---------------------------------------------------------------------------
// Phase 3: mean over batch -> scalar output
// ---------------------------------------------------------------------------
__global__ void reduce_kernel(float* out) {
    int tid = threadIdx.x;                   // 64 threads
    float v = g_nll[tid];
#pragma unroll
    for (int o = 16; o > 0; o >>= 1)
        v += __shfl_xor_sync(0xffffffffu, v, o);
    __shared__ float s[2];
    if ((tid & 31) == 0) s[tid >> 5] = v;
    __syncthreads();
    if (tid == 0) out[0] = (s[0] + s[1]) * (1.0f / NB);
}

extern "C" void kernel_launch(void* const* d_in, const int* in_sizes, int n_in,
                              void* d_out, int out_size) {
    const float*         hidden = (const float*)d_in[0];
    const float*         W      = (const float*)d_in[1];
    const float*         bias   = (const float*)d_in[2];
    const float*         startv = (const float*)d_in[3];
    const float*         endv   = (const float*)d_in[4];
    const float*         trans  = (const float*)d_in[5];
    const int*           labels = (const int*)d_in[6];
    const unsigned char* mask   = (const unsigned char*)d_in[7];

    gemm_kernel<<<1024, 256>>>(hidden, W, bias);
    crf_kernel<<<NB, 128>>>(startv, endv, trans, labels, mask);
    reduce_kernel<<<1, 64>>>((float*)d_out);
}